// round 8
// baseline (speedup 1.0000x reference)
#include <cuda_runtime.h>

// out[row] = alpha(||p||, ||p*w||) * (p*w), alpha folding expmap0 ->
// mobius diag -> project -> logmap0.
// 256-bit (v8.f32) global loads/stores: 6 memory instructions per row,
// 1 KB contiguous per warp-phase. Only m=p*w held through the scalar tail.

#define NCOLS 512
#define WARPS_PER_BLOCK 8

struct f8 { float4 lo, hi; };

__device__ __forceinline__ f8 ldg256_nc(const float* p)
{
    f8 v;
    asm volatile("ld.global.nc.v8.f32 {%0,%1,%2,%3,%4,%5,%6,%7}, [%8];"
                 : "=f"(v.lo.x), "=f"(v.lo.y), "=f"(v.lo.z), "=f"(v.lo.w),
                   "=f"(v.hi.x), "=f"(v.hi.y), "=f"(v.hi.z), "=f"(v.hi.w)
                 : "l"(p));
    return v;
}

__device__ __forceinline__ void stg256(float* p, const f8& v)
{
    asm volatile("st.global.v8.f32 [%0], {%1,%2,%3,%4,%5,%6,%7,%8};"
                 :: "l"(p),
                    "f"(v.lo.x), "f"(v.lo.y), "f"(v.lo.z), "f"(v.lo.w),
                    "f"(v.hi.x), "f"(v.hi.y), "f"(v.hi.z), "f"(v.hi.w)
                 : "memory");
}

__device__ __forceinline__ float fast_tanh_pos(float x)
{
    float t = __expf(-2.0f * x);
    return __fdividef(1.0f - t, 1.0f + t);
}

__device__ __forceinline__ float fast_atanh01(float x)
{
    return 0.5f * __logf(__fdividef(1.0f + x, 1.0f - x));
}

__global__ __launch_bounds__(WARPS_PER_BLOCK * 32, 8)
void hyp_adapter_kernel(const float* __restrict__ params,
                        const float* __restrict__ weights,
                        float* __restrict__ out,
                        int nrows)
{
    const int warp_global = (blockIdx.x * (WARPS_PER_BLOCK * 32) + threadIdx.x) >> 5;
    const int lane = threadIdx.x & 31;
    if (warp_global >= nrows) return;

    const float* __restrict__ prow = params + (size_t)warp_global * NCOLS;

    f8 m[2];                   // p*w — only vector state held through the tail
    float s1 = 0.0f;           // sum p^2
    float s2 = 0.0f;           // sum (p*w)^2

#pragma unroll
    for (int j = 0; j < 2; ++j) {
        const int off = j * 256 + lane * 8;   // floats
        f8 a = ldg256_nc(prow + off);
        f8 w = ldg256_nc(weights + off);

        s1 = fmaf(a.lo.x, a.lo.x, s1); s1 = fmaf(a.lo.y, a.lo.y, s1);
        s1 = fmaf(a.lo.z, a.lo.z, s1); s1 = fmaf(a.lo.w, a.lo.w, s1);
        s1 = fmaf(a.hi.x, a.hi.x, s1); s1 = fmaf(a.hi.y, a.hi.y, s1);
        s1 = fmaf(a.hi.z, a.hi.z, s1); s1 = fmaf(a.hi.w, a.hi.w, s1);

        m[j].lo.x = a.lo.x * w.lo.x; m[j].lo.y = a.lo.y * w.lo.y;
        m[j].lo.z = a.lo.z * w.lo.z; m[j].lo.w = a.lo.w * w.lo.w;
        m[j].hi.x = a.hi.x * w.hi.x; m[j].hi.y = a.hi.y * w.hi.y;
        m[j].hi.z = a.hi.z * w.hi.z; m[j].hi.w = a.hi.w * w.hi.w;

        s2 = fmaf(m[j].lo.x, m[j].lo.x, s2); s2 = fmaf(m[j].lo.y, m[j].lo.y, s2);
        s2 = fmaf(m[j].lo.z, m[j].lo.z, s2); s2 = fmaf(m[j].lo.w, m[j].lo.w, s2);
        s2 = fmaf(m[j].hi.x, m[j].hi.x, s2); s2 = fmaf(m[j].hi.y, m[j].hi.y, s2);
        s2 = fmaf(m[j].hi.z, m[j].hi.z, s2); s2 = fmaf(m[j].hi.w, m[j].hi.w, s2);
    }

#pragma unroll
    for (int off = 16; off > 0; off >>= 1) {
        s1 += __shfl_xor_sync(0xFFFFFFFFu, s1, off);
        s2 += __shfl_xor_sync(0xFFFFFFFFu, s2, off);
    }

    const float SQRT_C = 0.1f;
    const float EPS    = 1e-5f;
    const float MIN_N  = 1e-5f;

    float n1 = sqrtf(s1);                 // ||p||
    float n2 = sqrtf(s2);                 // ||p*w||

    // expmap0: x = s * p
    float u_norm = fmaxf(n1, MIN_N);
    float su = SQRT_C * u_norm;
    float s = __fdividef(fast_tanh_pos(su), su);

    // mobius diag scaling
    float x_norm  = fmaxf(s * n1, MIN_N);
    float mx_norm = s * n2;               // NOT clamped (matches torch)
    float cx = fminf(fmaxf(SQRT_C * x_norm, -1.0f + EPS), 1.0f - EPS);
    float at = fast_atanh01(cx);
    float tn = fast_tanh_pos(__fdividef(mx_norm, x_norm) * at);
    float beta = __fdividef(tn * s, mx_norm * SQRT_C);  // res = beta*(p*w)
    float res_norm = tn * (1.0f / SQRT_C);              // ||res||

    // project
    float rn = fmaxf(res_norm, MIN_N);
    float maxnorm = (1.0f - 0.001f) / SQRT_C;
    float gamma = (rn > maxnorm) ? __fdividef(maxnorm, rn) : 1.0f;

    // logmap0
    float y_norm = fmaxf(gamma * res_norm, MIN_N);
    float cy = fminf(fmaxf(SQRT_C * y_norm, -1.0f + EPS), 1.0f - EPS);
    float at2 = fast_atanh01(cy);
    float alpha = __fdividef(gamma * beta * at2, y_norm * SQRT_C);

    float* __restrict__ orow = out + (size_t)warp_global * NCOLS;
#pragma unroll
    for (int j = 0; j < 2; ++j) {
        f8 o;
        o.lo.x = alpha * m[j].lo.x; o.lo.y = alpha * m[j].lo.y;
        o.lo.z = alpha * m[j].lo.z; o.lo.w = alpha * m[j].lo.w;
        o.hi.x = alpha * m[j].hi.x; o.hi.y = alpha * m[j].hi.y;
        o.hi.z = alpha * m[j].hi.z; o.hi.w = alpha * m[j].hi.w;
        stg256(orow + j * 256 + lane * 8, o);
    }
}

extern "C" void kernel_launch(void* const* d_in, const int* in_sizes, int n_in,
                              void* d_out, int out_size)
{
    const float* params  = (const float*)d_in[0];
    const float* weights = (const float*)d_in[1];
    float* out = (float*)d_out;

    int nrows = in_sizes[0] / NCOLS;   // 131072
    int blocks = (nrows + WARPS_PER_BLOCK - 1) / WARPS_PER_BLOCK;

    hyp_adapter_kernel<<<blocks, WARPS_PER_BLOCK * 32>>>(params, weights, out, nrows);
}

// round 9
// speedup vs baseline: 1.0184x; 1.0184x over previous
#include <cuda_runtime.h>

// out[row] = alpha(||p_row||, ||p_row * w||) * (p_row * w)
// alpha folds expmap0 -> mobius diag scaling -> project -> logmap0 into one
// scalar per row. Single pass: row stays in registers, streaming cache hints.
// Converged configuration (session best: 82.0 us, DRAM ~80% = mixed-stream
// HBM ceiling on GB300; traffic 512 MB is irreducible).

#define NCOLS 512
#define WARPS_PER_BLOCK 8

__global__ __launch_bounds__(WARPS_PER_BLOCK * 32)
void hyp_adapter_kernel(const float* __restrict__ params,
                        const float* __restrict__ weights,
                        float* __restrict__ out,
                        int nrows)
{
    const int warp_global = (blockIdx.x * (WARPS_PER_BLOCK * 32) + threadIdx.x) >> 5;
    const int lane = threadIdx.x & 31;
    if (warp_global >= nrows) return;

    const float4* __restrict__ prow = reinterpret_cast<const float4*>(params) +
                                      (size_t)warp_global * (NCOLS / 4);
    const float4* __restrict__ w4 = reinterpret_cast<const float4*>(weights);

    float4 v[4];
    float4 wv[4];

    // Front-batch all loads: params streaming (evict-first), weights retained.
#pragma unroll
    for (int j = 0; j < 4; ++j) {
        v[j]  = __ldcs(&prow[j * 32 + lane]);
        wv[j] = __ldg(&w4[j * 32 + lane]);
    }

    float s1 = 0.0f;  // sum p^2
    float s2 = 0.0f;  // sum (p*w)^2
#pragma unroll
    for (int j = 0; j < 4; ++j) {
        float4 a = v[j], b = wv[j];
        s1 = fmaf(a.x, a.x, s1);
        s1 = fmaf(a.y, a.y, s1);
        s1 = fmaf(a.z, a.z, s1);
        s1 = fmaf(a.w, a.w, s1);
        float mx0 = a.x * b.x, mx1 = a.y * b.y, mx2 = a.z * b.z, mx3 = a.w * b.w;
        s2 = fmaf(mx0, mx0, s2);
        s2 = fmaf(mx1, mx1, s2);
        s2 = fmaf(mx2, mx2, s2);
        s2 = fmaf(mx3, mx3, s2);
    }

#pragma unroll
    for (int off = 16; off > 0; off >>= 1) {
        s1 += __shfl_xor_sync(0xFFFFFFFFu, s1, off);
        s2 += __shfl_xor_sync(0xFFFFFFFFu, s2, off);
    }

    const float SQRT_C = 0.1f;
    const float EPS    = 1e-5f;
    const float MIN_N  = 1e-5f;

    float n1 = sqrtf(s1);                 // ||p||
    float n2 = sqrtf(s2);                 // ||p*w||

    // expmap0: x = s * p
    float u_norm = fmaxf(n1, MIN_N);
    float su = SQRT_C * u_norm;
    float s = tanhf(su) / su;

    // mobius diag scaling
    float x_norm  = fmaxf(s * n1, MIN_N);
    float mx_norm = s * n2;               // NOT clamped (matches torch)
    float cx = fminf(fmaxf(SQRT_C * x_norm, -1.0f + EPS), 1.0f - EPS);
    float at = atanhf(cx);
    float tn = tanhf((mx_norm / x_norm) * at);
    float beta = tn * s / (mx_norm * SQRT_C);   // res = beta * (p*w)
    float res_norm = tn / SQRT_C;               // ||res||

    // project
    float rn = fmaxf(res_norm, MIN_N);
    float maxnorm = (1.0f - 0.001f) / SQRT_C;
    float gamma = (rn > maxnorm) ? (maxnorm / rn) : 1.0f;

    // logmap0
    float y_norm = fmaxf(gamma * res_norm, MIN_N);
    float cy = fminf(fmaxf(SQRT_C * y_norm, -1.0f + EPS), 1.0f - EPS);
    float at2 = atanhf(cy);
    float alpha = gamma * beta * at2 / (y_norm * SQRT_C);

    float4* __restrict__ orow = reinterpret_cast<float4*>(out) +
                                (size_t)warp_global * (NCOLS / 4);
#pragma unroll
    for (int j = 0; j < 4; ++j) {
        float4 a = v[j], b = wv[j];
        float4 o;
        o.x = alpha * (a.x * b.x);
        o.y = alpha * (a.y * b.y);
        o.z = alpha * (a.z * b.z);
        o.w = alpha * (a.w * b.w);
        __stcs(&orow[j * 32 + lane], o);
    }
}

extern "C" void kernel_launch(void* const* d_in, const int* in_sizes, int n_in,
                              void* d_out, int out_size)
{
    const float* params  = (const float*)d_in[0];
    const float* weights = (const float*)d_in[1];
    float* out = (float*)d_out;

    int nrows = in_sizes[0] / NCOLS;   // 131072
    int blocks = (nrows + WARPS_PER_BLOCK - 1) / WARPS_PER_BLOCK;

    hyp_adapter_kernel<<<blocks, WARPS_PER_BLOCK * 32>>>(params, weights, out, nrows);
}